// round 9
// baseline (speedup 1.0000x reference)
#include <cuda_runtime.h>
#include <cuda_bf16.h>
#include <math.h>
#include <stdint.h>

#define Bb 32
#define Nn 4096
#define Dd 512
#define Cc 64
#define NP (Bb*Nn)      // 131072 points
#define TM 128          // points per CTA tile
#define KS 64           // fp32 K elems per chunk
#define NCH (Dd/KS)     // 8 chunks

#define XPITCH 144      // bytes per smem row (64 bf16 + pad)
#define XBUFSZ 18432    // one x buffer: 128*144
#define AOFF 36864      // anchor double buffer base
#define ABUF 9216       // per-buffer anchors: 64*144
#define DS2OFF 33792    // epilogue: weight tile [64][128] fp32 (overlays anchors)
#define SMEM_DYN 66560
#define GS_PAD 65

#define SLICES 32       // pass-C slices per batch

// ---------------- scratch ----------------
__device__ float  d_anorm2[Cc];
__device__ float2 d_aux[Cc];        // {r0 = 1/sqrt(1+A2), invm = 1/(1+A2)}
__device__ int    d_counts[Bb*Cc];
__device__ int    d_index[Bb];
__device__ float  d_partial[Bb*SLICES*Dd];
__device__ __align__(16) __nv_bfloat16 d_ahi[Cc*Dd];
__device__ __align__(16) float d_scoreT[(size_t)Cc*NP];   // [C][B*N] candidate weights

// ---------------- helpers ----------------
__device__ __forceinline__ uint32_t smem_u32(const void* p) {
    uint32_t a;
    asm("{ .reg .u64 t; cvta.to.shared.u64 t, %1; cvt.u32.u64 %0, t; }" : "=r"(a) : "l"(p));
    return a;
}
#define STS64A(addr, a,b) \
    asm volatile("st.shared.v2.b32 [%0], {%1,%2};" :: "r"(addr),"r"(a),"r"(b) : "memory")

__device__ __forceinline__ void cpasync16(uint32_t dst, const void* src) {
    asm volatile("cp.async.ca.shared.global [%0], [%1], 16;" :: "r"(dst), "l"(src) : "memory");
}
#define CP_COMMIT() asm volatile("cp.async.commit_group;" ::: "memory")
#define CP_WAIT0()  asm volatile("cp.async.wait_group 0;" ::: "memory")

__device__ __forceinline__ void ldsm4(uint32_t* r, uint32_t a) {
    asm volatile("ldmatrix.sync.aligned.m8n8.x4.shared.b16 {%0,%1,%2,%3}, [%4];"
        : "=r"(r[0]),"=r"(r[1]),"=r"(r[2]),"=r"(r[3]) : "r"(a));
}
__device__ __forceinline__ void mma16816(float* c, const uint32_t* a, const uint32_t* b) {
    asm volatile("mma.sync.aligned.m16n8k16.row.col.f32.bf16.bf16.f32 "
        "{%0,%1,%2,%3}, {%4,%5,%6,%7}, {%8,%9}, {%0,%1,%2,%3};"
        : "+f"(c[0]),"+f"(c[1]),"+f"(c[2]),"+f"(c[3])
        : "r"(a[0]),"r"(a[1]),"r"(a[2]),"r"(a[3]), "r"(b[0]),"r"(b[1]));
}

// mask may arrive as int32 or int64; values in [1,4096] so high word of elem0 is 0 iff int64
__device__ __forceinline__ int read_mask(const void* m, int b) {
    const int* mi = (const int*)m;
    if (mi[1] == 0) return (int)(((const long long*)m)[b]);
    return mi[b];
}

// ---------------- K0: anchor norms/aux + bf16 convert + zero counts ----------------
__global__ void k0_init(const float* __restrict__ anchors) {
    __shared__ float wsum[8];
    int c = blockIdx.x, t = threadIdx.x, w = t >> 5, l = t & 31;
    if (c == 0) {
        for (int i = t; i < Bb*Cc; i += 256) d_counts[i] = 0;
    }
    float2 v = ((const float2*)(anchors + (size_t)c*Dd))[t];
    uint32_t lo = (uint32_t)__bfloat16_as_ushort(__float2bfloat16(v.x));
    uint32_t hi = (uint32_t)__bfloat16_as_ushort(__float2bfloat16(v.y));
    *(uint32_t*)&d_ahi[(size_t)c*Dd + 2*t] = lo | (hi << 16);
    float s = v.x*v.x + v.y*v.y;
    #pragma unroll
    for (int o = 16; o; o >>= 1) s += __shfl_xor_sync(0xffffffffu, s, o);
    if (l == 0) wsum[w] = s;
    __syncthreads();
    if (t == 0) {
        float tot = 0.f;
        #pragma unroll
        for (int j = 0; j < 8; j++) tot += wsum[j];
        d_anorm2[c] = tot;
        double m = 1.0 + (double)tot;
        d_aux[c] = make_float2((float)(1.0/sqrt(m)), (float)(1.0/m));
    }
}

// ---------------- KA: mma.sync bf16 GEMM (occ 3, batch-interleaved) ----------------
__global__ __launch_bounds__(256, 3)
void ka_mma(const float* __restrict__ x, const void* __restrict__ mask) {
    extern __shared__ __align__(16) char dsm[];
    __shared__ float rowsq[TM];
    __shared__ float s_sc[TM];
    __shared__ float sA2[Cc];
    __shared__ float2 sAux[Cc];
    __shared__ float s_h[2][TM];
    __shared__ int   s_ha[2][TM];

    int t = threadIdx.x, w = t >> 5, l = t & 31;
    int blk = blockIdx.x;
    int b = blk & 31, n0 = (blk >> 5) * TM;     // batch-interleaved mapping
    int maskb = read_mask(mask, b);
    if (n0 >= maskb) return;            // fully invalid tile

    if (t < Cc) { sA2[t] = d_anorm2[t]; sAux[t] = d_aux[t]; }
    uint32_t sb = smem_u32(dsm);

    // coalesced x staging: thread t -> rows r0+16j, float4 col c4
    int r0 = t >> 4, c4 = t & 15;
    const float* xgr = x + ((size_t)(b*Nn + n0) + r0) * Dd + c4*4;
    uint32_t sts0 = sb + (uint32_t)(r0*XPITCH + c4*8);
    // anchor cp.async mapping: row ra (0..63), quarter aq (16 bf16 = 32B)
    int ra = t >> 2, aq = t & 3;
    uint32_t adst = (uint32_t)(ra*XPITCH + aq*32);
    const __nv_bfloat16* ahsrc = d_ahi + (size_t)ra*Dd + aq*16;

    // ldmatrix lane addresses
    uint32_t mrow = (uint32_t)(w*16 + ((l>>3)&1)*8 + (l&7));
    uint32_t aAddrX = sb + mrow*XPITCH + ((l>>4)&1)*16;
    uint32_t nrb = (uint32_t)(((l>>4)&1)*8 + (l&7));
    uint32_t bkh = (uint32_t)((l>>3)&1)*16;
    uint32_t brel[4];
    #pragma unroll
    for (int q = 0; q < 4; q++) brel[q] = (uint32_t)((q*16 + nrb)*XPITCH) + bkh;

    float acc[8][4];
    #pragma unroll
    for (int j = 0; j < 8; j++)
        #pragma unroll
        for (int i = 0; i < 4; i++) acc[j][i] = 0.f;

    float ps[8];
    #pragma unroll
    for (int j = 0; j < 8; j++) ps[j] = 0.f;

    float4 v[4];

    // convert+store group of 4 rows (rows r0+16*(g0..g0+3)) into buffer bufsel
    auto cvst = [&](int g0, uint32_t bufbase) {
        #pragma unroll
        for (int j = 0; j < 4; j++) {
            float4 va = v[j];
            ps[g0+j] += va.x*va.x + va.y*va.y + va.z*va.z + va.w*va.w;
            uint32_t p0 = (uint32_t)__bfloat16_as_ushort(__float2bfloat16(va.x))
                        | ((uint32_t)__bfloat16_as_ushort(__float2bfloat16(va.y)) << 16);
            uint32_t p1 = (uint32_t)__bfloat16_as_ushort(__float2bfloat16(va.z))
                        | ((uint32_t)__bfloat16_as_ushort(__float2bfloat16(va.w)) << 16);
            STS64A(bufbase + (uint32_t)((g0+j)*16*XPITCH), p0, p1);
        }
    };

    // ---- prologue: anchors0 cp.async, x0 LDG+convert (2 groups) into buf0 ----
    {
        uint32_t d0 = sb + AOFF + adst;
        cpasync16(d0,      ahsrc);
        cpasync16(d0 + 16, ahsrc + 8);
        CP_COMMIT();
        #pragma unroll
        for (int j = 0; j < 4; j++) v[j] = *(const float4*)(xgr + (size_t)(16*j)*Dd);
        cvst(0, sts0);
        #pragma unroll
        for (int j = 0; j < 4; j++) v[j] = *(const float4*)(xgr + (size_t)(16*(j+4))*Dd);
        cvst(4, sts0);
        CP_WAIT0();
        __syncthreads();
    }

    // ---- main loop: one sync per chunk ----
    for (int it = 0; it < NCH; it++) {
        int nx = it + 1;
        uint32_t xA  = aAddrX + (uint32_t)((it&1)*XBUFSZ);
        uint32_t abH = sb + AOFF + (it&1)*ABUF;
        uint32_t sxn = sts0 + (uint32_t)((nx&1)*XBUFSZ);
        const float* xn = xgr + nx*KS;

        if (nx < NCH) {
            // anchors for next chunk first (longest latency chain)
            uint32_t d0 = sb + AOFF + (nx&1)*ABUF + adst;
            cpasync16(d0,      ahsrc + nx*KS);
            cpasync16(d0 + 16, ahsrc + nx*KS + 8);
            CP_COMMIT();
            // x group A loads
            #pragma unroll
            for (int j = 0; j < 4; j++) v[j] = *(const float4*)(xn + (size_t)(16*j)*Dd);
        }

        // MMA first half (ks 0..1)
        #pragma unroll
        for (int ks = 0; ks < 2; ks++) {
            uint32_t ko = ks*32;
            uint32_t ahf[4];
            ldsm4(ahf, xA + ko);
            #pragma unroll
            for (int hh = 0; hh < 2; hh++) {
                uint32_t bh[8];
                ldsm4(&bh[0], abH + brel[2*hh]   + ko);
                ldsm4(&bh[4], abH + brel[2*hh+1] + ko);
                mma16816(acc[4*hh+0], ahf, &bh[0]);
                mma16816(acc[4*hh+1], ahf, &bh[2]);
                mma16816(acc[4*hh+2], ahf, &bh[4]);
                mma16816(acc[4*hh+3], ahf, &bh[6]);
            }
        }

        if (nx < NCH) {
            cvst(0, sxn);       // store group A to opposite buffer (safe: MMA'd it-1)
            #pragma unroll
            for (int j = 0; j < 4; j++) v[j] = *(const float4*)(xn + (size_t)(16*(j+4))*Dd);
        }

        // MMA second half (ks 2..3)
        #pragma unroll
        for (int ks = 2; ks < 4; ks++) {
            uint32_t ko = ks*32;
            uint32_t ahf[4];
            ldsm4(ahf, xA + ko);
            #pragma unroll
            for (int hh = 0; hh < 2; hh++) {
                uint32_t bh[8];
                ldsm4(&bh[0], abH + brel[2*hh]   + ko);
                ldsm4(&bh[4], abH + brel[2*hh+1] + ko);
                mma16816(acc[4*hh+0], ahf, &bh[0]);
                mma16816(acc[4*hh+1], ahf, &bh[2]);
                mma16816(acc[4*hh+2], ahf, &bh[4]);
                mma16816(acc[4*hh+3], ahf, &bh[6]);
            }
        }

        if (nx < NCH) {
            cvst(4, sxn);
            CP_WAIT0();         // anchors(nx) landed
        }
        __syncthreads();
    }

    // row sumsq: reduce across the 16 lanes sharing each row
    {
        #pragma unroll
        for (int o = 1; o < 16; o <<= 1)
            #pragma unroll
            for (int j = 0; j < 8; j++)
                ps[j] += __shfl_xor_sync(0xffffffffu, ps[j], o);
        if (c4 == 0)
            #pragma unroll
            for (int j = 0; j < 8; j++) rowsq[r0 + 16*j] = ps[j];
    }

    __syncthreads();    // all MMA done; overlay D-tile fp32 [128][65] at smem base
    {
        float* ds = (float*)dsm;
        int row0 = w*16 + (l >> 2);
        int cb = 2*(l & 3);
        #pragma unroll
        for (int j = 0; j < 8; j++) {
            int col = j*8 + cb;
            ds[row0*GS_PAD + col]       = acc[j][0];
            ds[row0*GS_PAD + col + 1]   = acc[j][1];
            ds[(row0+8)*GS_PAD + col]   = acc[j][2];
            ds[(row0+8)*GS_PAD + col+1] = acc[j][3];
        }
    }
    __syncthreads();

    // ---- split-half epilogue: 256 threads, 2 threads per point ----
    int p    = t & 127;
    int half = t >> 7;
    int cb0  = half * 32;
    const float* ds = (const float*)dsm;
    float* ds2 = (float*)(dsm + DS2OFF);   // [64][128]

    float r2   = rowsq[p];
    float rr   = fmaxf(sqrtf(r2), 1e-12f);
    float invr = 1.0f / rr;
    float xnsq = r2 * invr * invr;
    float base = xnsq - 1.0f;
    float n2i  = -2.0f * invr;

    // pass 1: inv-dist cubic; per-half first-max
    float mx = -INFINITY;
    int arg = cb0;
    #pragma unroll 8
    for (int cc = 0; cc < 32; cc++) {
        int c = cb0 + cc;
        float g     = ds[p*GS_PAD + c];
        float2 aux  = sAux[c];
        float delta = fmaf(n2i, g, base);       // sq - (1+A2)
        float u     = delta * aux.y;
        float pp    = fmaf(u, -0.3125f, 0.375f);
        pp          = fmaf(u, pp, -0.5f);
        pp          = fmaf(u, pp, 1.0f);
        float inv   = aux.x * pp;
        if (u*u > 0.04f)                        // |u|>0.2: rare exact fallback
            inv = rsqrtf(fmaxf(delta + 1.0f + sA2[c], 1e-24f));
        ds2[c*TM + p] = inv;
        if (inv > mx) { mx = inv; arg = c; }
    }
    s_h[half][p] = mx; s_ha[half][p] = arg;
    __syncthreads();
    float m0 = s_h[0][p], m1 = s_h[1][p];
    float mxc = (m1 > m0) ? m1 : m0;
    int argc = (m1 > m0) ? s_ha[1][p] : s_ha[0][p];   // tie -> half0 (lower c) = first-max
    __syncthreads();

    // pass 2: cubic exp(inv - mx)
    float Z = 0.f;
    #pragma unroll 8
    for (int cc = 0; cc < 32; cc++) {
        int c = cb0 + cc;
        float u2 = ds2[c*TM + p] - mxc;
        float e  = fmaf(u2, 0.16666667f, 0.5f);
        e        = fmaf(u2, e, 1.0f);
        e        = fmaf(u2, e, 1.0f);
        if (u2 < -0.0625f) e = expf(u2);        // rare exact fallback
        Z += e;
        ds2[c*TM + p] = e;
    }
    s_h[half][p] = Z;
    __syncthreads();
    if (half == 0) {
        s_sc[p] = invr / (s_h[0][p] + s_h[1][p]);
        int n = n0 + p;
        if (n < maskb) atomicAdd(&d_counts[b*Cc + argc], 1);
    }
    __syncthreads();

    // coalesced transposed score store with per-row scale folded in
    {
        int bpos = b*Nn + n0;
        for (int i = t; i < Cc*TM; i += 256) {
            int c = i >> 7, rr2 = i & (TM-1);
            d_scoreT[(size_t)c*NP + bpos + rr2] = ds2[i] * s_sc[rr2];
        }
    }
}

// ---------------- KB: per-batch mode cluster (warp-parallel, first-max) ----------------
__global__ void kb_index() {
    int b = blockIdx.x, l = threadIdx.x;
    int v0 = d_counts[b*Cc + l];
    int v1 = d_counts[b*Cc + l + 32];
    int p0 = (v0 << 6) | (63 - l);
    int p1 = (v1 << 6) | (63 - (l + 32));
    int p = max(p0, p1);
    #pragma unroll
    for (int o = 16; o; o >>= 1) p = max(p, __shfl_xor_sync(0xffffffffu, p, o));
    if (l == 0) d_index[b] = 63 - (p & 63);
}

// ---------------- KC: pure streaming weighted sum (batch-interleaved) ----------------
__global__ __launch_bounds__(256, 4)
void kc_feature(const float* __restrict__ x, const void* __restrict__ mask) {
    __shared__ float sfeat[Dd];
    int t = threadIdx.x, w = t >> 5, l = t & 31;
    int b = blockIdx.x & 31, s = blockIdx.x >> 5;   // batch-interleaved mapping
    int maskb = read_mask(mask, b);
    int idx = d_index[b];
    const float* scp = d_scoreT + (size_t)idx*NP + (size_t)b*Nn;
    const float* xb  = x + (size_t)b*Nn*Dd;

    float4 acc[4];
    #pragma unroll
    for (int j = 0; j < 4; j++) acc[j] = make_float4(0.f,0.f,0.f,0.f);

    int ws = (s << 3) + w;                      // warp slot 0..255
    for (int n = ws; n < maskb; n += 512) {
        int n2 = n + 256;
        bool has2 = n2 < maskb;
        int n2c = has2 ? n2 : n;
        float w1 = __ldg(scp + n);
        float w2 = has2 ? __ldg(scp + n2) : 0.f;
        const float4* xp1 = (const float4*)(xb + (size_t)n*Dd);
        const float4* xp2 = (const float4*)(xb + (size_t)n2c*Dd);
        float4 x1[4], x2[4];
        #pragma unroll
        for (int j = 0; j < 4; j++) { x1[j] = xp1[l + 32*j]; x2[j] = xp2[l + 32*j]; }
        #pragma unroll
        for (int j = 0; j < 4; j++) {
            acc[j].x += x1[j].x*w1 + x2[j].x*w2;
            acc[j].y += x1[j].y*w1 + x2[j].y*w2;
            acc[j].z += x1[j].z*w1 + x2[j].z*w2;
            acc[j].w += x1[j].w*w1 + x2[j].w*w2;
        }
    }

    sfeat[t] = 0.f; sfeat[t + 256] = 0.f;
    __syncthreads();
    #pragma unroll
    for (int j = 0; j < 4; j++) {
        int base = 4*(l + 32*j);
        atomicAdd(&sfeat[base+0], acc[j].x);
        atomicAdd(&sfeat[base+1], acc[j].y);
        atomicAdd(&sfeat[base+2], acc[j].z);
        atomicAdd(&sfeat[base+3], acc[j].w);
    }
    __syncthreads();
    // d_partial indexed by (b, s) regardless of block mapping
    float* pp = &d_partial[(size_t)(b*SLICES + s) * Dd];
    pp[t] = sfeat[t]; pp[t + 256] = sfeat[t + 256];
}

// ---------------- KD: deterministic partial reduction ----------------
__global__ void kd_reduce(float* __restrict__ out) {
    int b = blockIdx.x, t = threadIdx.x;
    for (int d = t; d < Dd; d += 256) {
        float s = 0.f;
        #pragma unroll 8
        for (int j = 0; j < SLICES; j++)
            s += d_partial[(size_t)(b*SLICES + j)*Dd + d];
        out[b*Dd + d] = s;
    }
}

extern "C" void kernel_launch(void* const* d_in, const int* in_sizes, int n_in,
                              void* d_out, int out_size) {
    const float* x       = (const float*)d_in[0];
    const void*  mask    = d_in[1];
    const float* anchors = (const float*)d_in[2];
    float* out = (float*)d_out;

    cudaFuncSetAttribute(ka_mma, cudaFuncAttributeMaxDynamicSharedMemorySize, SMEM_DYN);

    k0_init<<<Cc, 256>>>(anchors);
    ka_mma<<<NP/TM, 256, SMEM_DYN>>>(x, mask);          // 1024 CTAs
    kb_index<<<Bb, 32>>>();
    kc_feature<<<Bb*SLICES, 256>>>(x, mask);            // 1024 CTAs
    kd_reduce<<<Bb, 256>>>(out);
}

// round 10
// speedup vs baseline: 1.0462x; 1.0462x over previous
#include <cuda_runtime.h>
#include <cuda_bf16.h>
#include <math.h>
#include <stdint.h>

#define Bb 32
#define Nn 4096
#define Dd 512
#define Cc 64
#define NP (Bb*Nn)      // 131072 points
#define TM 128          // points per CTA tile
#define KS 64           // fp32 K elems per chunk
#define NCH (Dd/KS)     // 8 chunks

#define XPITCH 144      // bytes per smem row (64 bf16 + pad)
#define XBUFSZ 18432    // one x buffer: 128*144
#define AOFF 36864      // anchor double buffer base
#define ABUF 9216       // per-buffer anchors: 64*144
#define DS2OFF 55296    // candidate-weight tile [64][128] fp32
#define SMEM_DYN 88064  // 55296 + 32768
#define GS_PAD 65

#define SLICES 64       // pass-C slices per batch (finer for tail balance)

// ---------------- scratch ----------------
__device__ float  d_anorm2[Cc];
__device__ float2 d_aux[Cc];        // {r0 = 1/sqrt(1+A2), invm = 1/(1+A2)}
__device__ int    d_counts[Bb*Cc];
__device__ int    d_index[Bb];
__device__ float  d_partial[Bb*SLICES*Dd];
__device__ __align__(16) __nv_bfloat16 d_ahi[Cc*Dd];
__device__ __align__(16) float d_scoreT[(size_t)Cc*NP];   // [C][B*N] candidate weights

// ---------------- helpers ----------------
__device__ __forceinline__ uint32_t smem_u32(const void* p) {
    uint32_t a;
    asm("{ .reg .u64 t; cvta.to.shared.u64 t, %1; cvt.u32.u64 %0, t; }" : "=r"(a) : "l"(p));
    return a;
}
#define STS64A(addr, a,b) \
    asm volatile("st.shared.v2.b32 [%0], {%1,%2};" :: "r"(addr),"r"(a),"r"(b) : "memory")

__device__ __forceinline__ void cpasync16(uint32_t dst, const void* src) {
    asm volatile("cp.async.ca.shared.global [%0], [%1], 16;" :: "r"(dst), "l"(src) : "memory");
}
#define CP_COMMIT() asm volatile("cp.async.commit_group;" ::: "memory")
#define CP_WAIT0()  asm volatile("cp.async.wait_group 0;" ::: "memory")

__device__ __forceinline__ void ldsm4(uint32_t* r, uint32_t a) {
    asm volatile("ldmatrix.sync.aligned.m8n8.x4.shared.b16 {%0,%1,%2,%3}, [%4];"
        : "=r"(r[0]),"=r"(r[1]),"=r"(r[2]),"=r"(r[3]) : "r"(a));
}
__device__ __forceinline__ void mma16816(float* c, const uint32_t* a, const uint32_t* b) {
    asm volatile("mma.sync.aligned.m16n8k16.row.col.f32.bf16.bf16.f32 "
        "{%0,%1,%2,%3}, {%4,%5,%6,%7}, {%8,%9}, {%0,%1,%2,%3};"
        : "+f"(c[0]),"+f"(c[1]),"+f"(c[2]),"+f"(c[3])
        : "r"(a[0]),"r"(a[1]),"r"(a[2]),"r"(a[3]), "r"(b[0]),"r"(b[1]));
}

// mask may arrive as int32 or int64; values in [1,4096] so high word of elem0 is 0 iff int64
__device__ __forceinline__ int read_mask(const void* m, int b) {
    const int* mi = (const int*)m;
    if (mi[1] == 0) return (int)(((const long long*)m)[b]);
    return mi[b];
}

// ---------------- K0: anchor norms/aux + bf16 convert + zero counts ----------------
__global__ void k0_init(const float* __restrict__ anchors) {
    __shared__ float wsum[8];
    int c = blockIdx.x, t = threadIdx.x, w = t >> 5, l = t & 31;
    if (c == 0) {
        for (int i = t; i < Bb*Cc; i += 256) d_counts[i] = 0;
    }
    float2 v = ((const float2*)(anchors + (size_t)c*Dd))[t];
    uint32_t lo = (uint32_t)__bfloat16_as_ushort(__float2bfloat16(v.x));
    uint32_t hi = (uint32_t)__bfloat16_as_ushort(__float2bfloat16(v.y));
    *(uint32_t*)&d_ahi[(size_t)c*Dd + 2*t] = lo | (hi << 16);
    float s = v.x*v.x + v.y*v.y;
    #pragma unroll
    for (int o = 16; o; o >>= 1) s += __shfl_xor_sync(0xffffffffu, s, o);
    if (l == 0) wsum[w] = s;
    __syncthreads();
    if (t == 0) {
        float tot = 0.f;
        #pragma unroll
        for (int j = 0; j < 8; j++) tot += wsum[j];
        d_anorm2[c] = tot;
        double m = 1.0 + (double)tot;
        d_aux[c] = make_float2((float)(1.0/sqrt(m)), (float)(1.0/m));
    }
}

// ---------------- KA: mma.sync bf16 GEMM (double-buffered, occ 2) + poly softmax ----------------
__global__ __launch_bounds__(256, 2)
void ka_mma(const float* __restrict__ x, const void* __restrict__ mask) {
    extern __shared__ __align__(16) char dsm[];
    __shared__ float rowsq[TM];
    __shared__ float s_sc[TM];
    __shared__ float sA2[Cc];
    __shared__ float2 sAux[Cc];
    __shared__ float s_h[2][TM];
    __shared__ int   s_ha[2][TM];

    int t = threadIdx.x, w = t >> 5, l = t & 31;
    int blk = blockIdx.x;
    int b = blk >> 5, n0 = (blk & 31) * TM;
    int maskb = read_mask(mask, b);
    if (n0 >= maskb) return;            // fully invalid tile

    if (t < Cc) { sA2[t] = d_anorm2[t]; sAux[t] = d_aux[t]; }
    uint32_t sb = smem_u32(dsm);

    // coalesced x staging: thread t -> rows r0+16j (j=0..7), float4 col c4
    int r0 = t >> 4, c4 = t & 15;
    const float* xgr = x + ((size_t)(b*Nn + n0) + r0) * Dd + c4*4;
    uint32_t sts0 = sb + (uint32_t)(r0*XPITCH + c4*8);
    // anchor cp.async mapping: row ra (0..63), quarter aq (16 bf16 = 32B)
    int ra = t >> 2, aq = t & 3;
    uint32_t adst = (uint32_t)(ra*XPITCH + aq*32);
    const __nv_bfloat16* ahsrc = d_ahi + (size_t)ra*Dd + aq*16;

    // ldmatrix lane addresses
    uint32_t mrow = (uint32_t)(w*16 + ((l>>3)&1)*8 + (l&7));
    uint32_t aAddrX = sb + mrow*XPITCH + ((l>>4)&1)*16;
    uint32_t nrb = (uint32_t)(((l>>4)&1)*8 + (l&7));
    uint32_t bkh = (uint32_t)((l>>3)&1)*16;
    uint32_t brel[4];
    #pragma unroll
    for (int q = 0; q < 4; q++) brel[q] = (uint32_t)((q*16 + nrb)*XPITCH) + bkh;

    float acc[8][4];
    #pragma unroll
    for (int j = 0; j < 8; j++)
        #pragma unroll
        for (int i = 0; i < 4; i++) acc[j][i] = 0.f;

    float ps[8];        // per-row sumsq partials (row r0+16j)
    #pragma unroll
    for (int j = 0; j < 8; j++) ps[j] = 0.f;

    float4 v[8];

    // ---- prologue: anchors0 cp.async, x0 LDG + convert into buf0 ----
    {
        uint32_t d0 = sb + AOFF + adst;
        cpasync16(d0,      ahsrc);
        cpasync16(d0 + 16, ahsrc + 8);
        CP_COMMIT();
        #pragma unroll
        for (int j = 0; j < 8; j++)
            v[j] = *(const float4*)(xgr + (size_t)(16*j)*Dd);
        #pragma unroll
        for (int j = 0; j < 8; j++) {
            float4 va = v[j];
            ps[j] += va.x*va.x + va.y*va.y + va.z*va.z + va.w*va.w;
            uint32_t p0 = (uint32_t)__bfloat16_as_ushort(__float2bfloat16(va.x))
                        | ((uint32_t)__bfloat16_as_ushort(__float2bfloat16(va.y)) << 16);
            uint32_t p1 = (uint32_t)__bfloat16_as_ushort(__float2bfloat16(va.z))
                        | ((uint32_t)__bfloat16_as_ushort(__float2bfloat16(va.w)) << 16);
            STS64A(sts0 + (uint32_t)(j*16*XPITCH), p0, p1);
        }
        CP_WAIT0();
        __syncthreads();
    }

    // ---- main loop: one sync per chunk ----
    for (int it = 0; it < NCH; it++) {
        int nx = it + 1;
        if (nx < NCH) {
            // LDG next x early (latency hides under MMA)
            const float* xn = xgr + nx*KS;
            #pragma unroll
            for (int j = 0; j < 8; j++)
                v[j] = *(const float4*)(xn + (size_t)(16*j)*Dd);
            // anchors for next chunk -> opposite buffer (safe: last read it-1)
            uint32_t d0 = sb + AOFF + (nx&1)*ABUF + adst;
            cpasync16(d0,      ahsrc + nx*KS);
            cpasync16(d0 + 16, ahsrc + nx*KS + 8);
            CP_COMMIT();
        }

        // MMA on buffers it&1
        uint32_t xA  = aAddrX + (uint32_t)((it&1)*XBUFSZ);
        uint32_t abH = sb + AOFF + (it&1)*ABUF;
        #pragma unroll
        for (int ks = 0; ks < 4; ks++) {
            uint32_t ko = ks*32;
            uint32_t ahf[4];
            ldsm4(ahf, xA + ko);
            #pragma unroll
            for (int hh = 0; hh < 2; hh++) {
                uint32_t bh[8];
                ldsm4(&bh[0], abH + brel[2*hh]   + ko);
                ldsm4(&bh[4], abH + brel[2*hh+1] + ko);
                mma16816(acc[4*hh+0], ahf, &bh[0]);
                mma16816(acc[4*hh+1], ahf, &bh[2]);
                mma16816(acc[4*hh+2], ahf, &bh[4]);
                mma16816(acc[4*hh+3], ahf, &bh[6]);
            }
        }

        // convert + store next x chunk into opposite buffer
        if (nx < NCH) {
            uint32_t sx = sts0 + (uint32_t)((nx&1)*XBUFSZ);
            #pragma unroll
            for (int j = 0; j < 8; j++) {
                float4 va = v[j];
                ps[j] += va.x*va.x + va.y*va.y + va.z*va.z + va.w*va.w;
                uint32_t p0 = (uint32_t)__bfloat16_as_ushort(__float2bfloat16(va.x))
                            | ((uint32_t)__bfloat16_as_ushort(__float2bfloat16(va.y)) << 16);
                uint32_t p1 = (uint32_t)__bfloat16_as_ushort(__float2bfloat16(va.z))
                            | ((uint32_t)__bfloat16_as_ushort(__float2bfloat16(va.w)) << 16);
                STS64A(sx + (uint32_t)(j*16*XPITCH), p0, p1);
            }
            CP_WAIT0();     // anchors(nx) landed
        }
        __syncthreads();
    }

    // row sumsq: reduce across the 16 lanes sharing each row
    {
        #pragma unroll
        for (int o = 1; o < 16; o <<= 1)
            #pragma unroll
            for (int j = 0; j < 8; j++)
                ps[j] += __shfl_xor_sync(0xffffffffu, ps[j], o);
        if (c4 == 0)
            #pragma unroll
            for (int j = 0; j < 8; j++) rowsq[r0 + 16*j] = ps[j];
    }

    __syncthreads();    // all MMA done; overlay D-tile fp32 [128][65] on x buffers
    {
        float* ds = (float*)dsm;
        int row0 = w*16 + (l >> 2);
        int cb = 2*(l & 3);
        #pragma unroll
        for (int j = 0; j < 8; j++) {
            int col = j*8 + cb;
            ds[row0*GS_PAD + col]       = acc[j][0];
            ds[row0*GS_PAD + col + 1]   = acc[j][1];
            ds[(row0+8)*GS_PAD + col]   = acc[j][2];
            ds[(row0+8)*GS_PAD + col+1] = acc[j][3];
        }
    }
    __syncthreads();

    // ---- split-half epilogue: 256 threads, 2 threads per point ----
    int p    = t & 127;
    int half = t >> 7;
    int cb0  = half * 32;
    const float* ds = (const float*)dsm;
    float* ds2 = (float*)(dsm + DS2OFF);   // [64][128]

    float r2   = rowsq[p];
    float rr   = fmaxf(sqrtf(r2), 1e-12f);
    float invr = 1.0f / rr;
    float xnsq = r2 * invr * invr;
    float base = xnsq - 1.0f;
    float n2i  = -2.0f * invr;

    // pass 1: inv-dist cubic; per-half first-max
    float mx = -INFINITY;
    int arg = cb0;
    #pragma unroll 8
    for (int cc = 0; cc < 32; cc++) {
        int c = cb0 + cc;
        float g     = ds[p*GS_PAD + c];
        float2 aux  = sAux[c];
        float delta = fmaf(n2i, g, base);       // sq - (1+A2)
        float u     = delta * aux.y;
        float pp    = fmaf(u, -0.3125f, 0.375f);
        pp          = fmaf(u, pp, -0.5f);
        pp          = fmaf(u, pp, 1.0f);
        float inv   = aux.x * pp;
        if (u*u > 0.04f)                        // |u|>0.2: rare exact fallback
            inv = rsqrtf(fmaxf(delta + 1.0f + sA2[c], 1e-24f));
        ds2[c*TM + p] = inv;
        if (inv > mx) { mx = inv; arg = c; }
    }
    s_h[half][p] = mx; s_ha[half][p] = arg;
    __syncthreads();
    float m0 = s_h[0][p], m1 = s_h[1][p];
    float mxc = (m1 > m0) ? m1 : m0;
    int argc = (m1 > m0) ? s_ha[1][p] : s_ha[0][p];   // tie -> half0 (lower c) = first-max
    __syncthreads();

    // pass 2: cubic exp(inv - mx)
    float Z = 0.f;
    #pragma unroll 8
    for (int cc = 0; cc < 32; cc++) {
        int c = cb0 + cc;
        float u2 = ds2[c*TM + p] - mxc;
        float e  = fmaf(u2, 0.16666667f, 0.5f);
        e        = fmaf(u2, e, 1.0f);
        e        = fmaf(u2, e, 1.0f);
        if (u2 < -0.0625f) e = expf(u2);        // rare exact fallback
        Z += e;
        ds2[c*TM + p] = e;
    }
    s_h[half][p] = Z;
    __syncthreads();
    if (half == 0) {
        s_sc[p] = invr / (s_h[0][p] + s_h[1][p]);
        int n = n0 + p;
        if (n < maskb) atomicAdd(&d_counts[b*Cc + argc], 1);
    }
    __syncthreads();

    // coalesced transposed score store with per-row scale folded in
    {
        int bpos = blk * TM;
        for (int i = t; i < Cc*TM; i += 256) {
            int c = i >> 7, rr2 = i & (TM-1);
            d_scoreT[(size_t)c*NP + bpos + rr2] = ds2[i] * s_sc[rr2];
        }
    }
}

// ---------------- KB: per-batch mode cluster (warp-parallel, first-max) ----------------
__global__ void kb_index() {
    int b = blockIdx.x, l = threadIdx.x;
    int v0 = d_counts[b*Cc + l];
    int v1 = d_counts[b*Cc + l + 32];
    // pack: count<<6 | (63-c)  -> max picks highest count, lowest c on tie
    int p0 = (v0 << 6) | (63 - l);
    int p1 = (v1 << 6) | (63 - (l + 32));
    int p = max(p0, p1);
    #pragma unroll
    for (int o = 16; o; o >>= 1) p = max(p, __shfl_xor_sync(0xffffffffu, p, o));
    if (l == 0) d_index[b] = 63 - (p & 63);
}

// ---------------- KC: pure streaming weighted sum (finer slices for tail balance) ----------------
__global__ __launch_bounds__(256, 4)
void kc_feature(const float* __restrict__ x, const void* __restrict__ mask) {
    __shared__ float sfeat[Dd];
    int t = threadIdx.x, w = t >> 5, l = t & 31;
    int b = blockIdx.x / SLICES, s = blockIdx.x % SLICES;   // b-major (locality)
    int maskb = read_mask(mask, b);
    int idx = d_index[b];
    const float* scp = d_scoreT + (size_t)idx*NP + (size_t)b*Nn;
    const float* xb  = x + (size_t)b*Nn*Dd;

    float4 acc[4];
    #pragma unroll
    for (int j = 0; j < 4; j++) acc[j] = make_float4(0.f,0.f,0.f,0.f);

    int ws = (s << 3) + w;                      // warp slot 0..511
    for (int n = ws; n < maskb; n += 1024) {
        int n2 = n + 512;
        bool has2 = n2 < maskb;
        int n2c = has2 ? n2 : n;
        float w1 = __ldg(scp + n);
        float w2 = has2 ? __ldg(scp + n2) : 0.f;
        const float4* xp1 = (const float4*)(xb + (size_t)n*Dd);
        const float4* xp2 = (const float4*)(xb + (size_t)n2c*Dd);
        float4 x1[4], x2[4];
        #pragma unroll
        for (int j = 0; j < 4; j++) { x1[j] = xp1[l + 32*j]; x2[j] = xp2[l + 32*j]; }
        #pragma unroll
        for (int j = 0; j < 4; j++) {
            acc[j].x += x1[j].x*w1 + x2[j].x*w2;
            acc[j].y += x1[j].y*w1 + x2[j].y*w2;
            acc[j].z += x1[j].z*w1 + x2[j].z*w2;
            acc[j].w += x1[j].w*w1 + x2[j].w*w2;
        }
    }

    sfeat[t] = 0.f; sfeat[t + 256] = 0.f;
    __syncthreads();
    #pragma unroll
    for (int j = 0; j < 4; j++) {
        int base = 4*(l + 32*j);
        atomicAdd(&sfeat[base+0], acc[j].x);
        atomicAdd(&sfeat[base+1], acc[j].y);
        atomicAdd(&sfeat[base+2], acc[j].z);
        atomicAdd(&sfeat[base+3], acc[j].w);
    }
    __syncthreads();
    float* pp = &d_partial[(size_t)(b*SLICES + s) * Dd];
    pp[t] = sfeat[t]; pp[t + 256] = sfeat[t + 256];
}

// ---------------- KD: deterministic partial reduction ----------------
__global__ void kd_reduce(float* __restrict__ out) {
    int b = blockIdx.x, t = threadIdx.x;
    for (int d = t; d < Dd; d += 256) {
        float s = 0.f;
        #pragma unroll 8
        for (int j = 0; j < SLICES; j++)
            s += d_partial[(size_t)(b*SLICES + j)*Dd + d];
        out[b*Dd + d] = s;
    }
}

extern "C" void kernel_launch(void* const* d_in, const int* in_sizes, int n_in,
                              void* d_out, int out_size) {
    const float* x       = (const float*)d_in[0];
    const void*  mask    = d_in[1];
    const float* anchors = (const float*)d_in[2];
    float* out = (float*)d_out;

    cudaFuncSetAttribute(ka_mma, cudaFuncAttributeMaxDynamicSharedMemorySize, SMEM_DYN);

    k0_init<<<Cc, 256>>>(anchors);
    ka_mma<<<NP/TM, 256, SMEM_DYN>>>(x, mask);          // 1024 CTAs
    kb_index<<<Bb, 32>>>();
    kc_feature<<<Bb*SLICES, 256>>>(x, mask);            // 2048 CTAs
    kd_reduce<<<Bb, 256>>>(out);
}

// round 11
// speedup vs baseline: 1.2107x; 1.1572x over previous
#include <cuda_runtime.h>
#include <cuda_bf16.h>
#include <cuda_fp16.h>
#include <math.h>
#include <stdint.h>

#define Bb 32
#define Nn 4096
#define Dd 512
#define Cc 64
#define NP (Bb*Nn)      // 131072 points
#define TM 128          // points per CTA tile
#define KS 64           // fp32 K elems per chunk
#define NCH (Dd/KS)     // 8 chunks

#define XPITCH 144      // bytes per smem row (64 bf16 + pad)
#define XBUFSZ 18432    // one x buffer: 128*144
#define AOFF 36864      // anchor double buffer base
#define ABUF 9216       // per-buffer anchors: 64*144
#define DS2OFF 55296    // candidate-weight tile [64][128] fp32
#define SMEM_DYN 88064  // 55296 + 32768
#define GS_PAD 65

#define SLICES 32       // pass-C slices per batch

// ---------------- scratch ----------------
__device__ float  d_anorm2[Cc];
__device__ float2 d_aux[Cc];        // {r0 = 1/sqrt(1+A2), invm = 1/(1+A2)}
__device__ int    d_counts[Bb*Cc];
__device__ int    d_index[Bb];
__device__ float  d_partial[Bb*SLICES*Dd];
__device__ __align__(16) __nv_bfloat16 d_ahi[Cc*Dd];
__device__ __align__(16) __half d_scoreT[(size_t)Cc*NP];  // [C][B*N] fp16 weights

// ---------------- helpers ----------------
__device__ __forceinline__ uint32_t smem_u32(const void* p) {
    uint32_t a;
    asm("{ .reg .u64 t; cvta.to.shared.u64 t, %1; cvt.u32.u64 %0, t; }" : "=r"(a) : "l"(p));
    return a;
}
#define STS64A(addr, a,b) \
    asm volatile("st.shared.v2.b32 [%0], {%1,%2};" :: "r"(addr),"r"(a),"r"(b) : "memory")

__device__ __forceinline__ void cpasync16(uint32_t dst, const void* src) {
    asm volatile("cp.async.ca.shared.global [%0], [%1], 16;" :: "r"(dst), "l"(src) : "memory");
}
#define CP_COMMIT() asm volatile("cp.async.commit_group;" ::: "memory")
#define CP_WAIT0()  asm volatile("cp.async.wait_group 0;" ::: "memory")

__device__ __forceinline__ void ldsm4(uint32_t* r, uint32_t a) {
    asm volatile("ldmatrix.sync.aligned.m8n8.x4.shared.b16 {%0,%1,%2,%3}, [%4];"
        : "=r"(r[0]),"=r"(r[1]),"=r"(r[2]),"=r"(r[3]) : "r"(a));
}
__device__ __forceinline__ void mma16816(float* c, const uint32_t* a, const uint32_t* b) {
    asm volatile("mma.sync.aligned.m16n8k16.row.col.f32.bf16.bf16.f32 "
        "{%0,%1,%2,%3}, {%4,%5,%6,%7}, {%8,%9}, {%0,%1,%2,%3};"
        : "+f"(c[0]),"+f"(c[1]),"+f"(c[2]),"+f"(c[3])
        : "r"(a[0]),"r"(a[1]),"r"(a[2]),"r"(a[3]), "r"(b[0]),"r"(b[1]));
}

// mask may arrive as int32 or int64; values in [1,4096] so high word of elem0 is 0 iff int64
__device__ __forceinline__ int read_mask(const void* m, int b) {
    const int* mi = (const int*)m;
    if (mi[1] == 0) return (int)(((const long long*)m)[b]);
    return mi[b];
}

// ---------------- K0: anchor norms/aux + bf16 convert + zero counts ----------------
__global__ void k0_init(const float* __restrict__ anchors) {
    __shared__ float wsum[8];
    int c = blockIdx.x, t = threadIdx.x, w = t >> 5, l = t & 31;
    if (c == 0) {
        for (int i = t; i < Bb*Cc; i += 256) d_counts[i] = 0;
    }
    float2 v = ((const float2*)(anchors + (size_t)c*Dd))[t];
    uint32_t lo = (uint32_t)__bfloat16_as_ushort(__float2bfloat16(v.x));
    uint32_t hi = (uint32_t)__bfloat16_as_ushort(__float2bfloat16(v.y));
    *(uint32_t*)&d_ahi[(size_t)c*Dd + 2*t] = lo | (hi << 16);
    float s = v.x*v.x + v.y*v.y;
    #pragma unroll
    for (int o = 16; o; o >>= 1) s += __shfl_xor_sync(0xffffffffu, s, o);
    if (l == 0) wsum[w] = s;
    __syncthreads();
    if (t == 0) {
        float tot = 0.f;
        #pragma unroll
        for (int j = 0; j < 8; j++) tot += wsum[j];
        d_anorm2[c] = tot;
        double m = 1.0 + (double)tot;
        d_aux[c] = make_float2((float)(1.0/sqrt(m)), (float)(1.0/m));
    }
}

// ---------------- KA: mma.sync bf16 GEMM (double-buffered, occ 2) + poly softmax ----------------
__global__ __launch_bounds__(256, 2)
void ka_mma(const float* __restrict__ x, const void* __restrict__ mask) {
    extern __shared__ __align__(16) char dsm[];
    __shared__ float rowsq[TM];
    __shared__ float s_sc[TM];
    __shared__ float sA2[Cc];
    __shared__ float2 sAux[Cc];
    __shared__ float s_h[2][TM];
    __shared__ int   s_ha[2][TM];

    int t = threadIdx.x, w = t >> 5, l = t & 31;
    int blk = blockIdx.x;
    int b = blk >> 5, n0 = (blk & 31) * TM;
    int maskb = read_mask(mask, b);
    if (n0 >= maskb) return;            // fully invalid tile

    if (t < Cc) { sA2[t] = d_anorm2[t]; sAux[t] = d_aux[t]; }
    uint32_t sb = smem_u32(dsm);

    // coalesced x staging: thread t -> rows r0+16j (j=0..7), float4 col c4
    int r0 = t >> 4, c4 = t & 15;
    const float* xgr = x + ((size_t)(b*Nn + n0) + r0) * Dd + c4*4;
    uint32_t sts0 = sb + (uint32_t)(r0*XPITCH + c4*8);
    // anchor cp.async mapping: row ra (0..63), quarter aq (16 bf16 = 32B)
    int ra = t >> 2, aq = t & 3;
    uint32_t adst = (uint32_t)(ra*XPITCH + aq*32);
    const __nv_bfloat16* ahsrc = d_ahi + (size_t)ra*Dd + aq*16;

    // ldmatrix lane addresses
    uint32_t mrow = (uint32_t)(w*16 + ((l>>3)&1)*8 + (l&7));
    uint32_t aAddrX = sb + mrow*XPITCH + ((l>>4)&1)*16;
    uint32_t nrb = (uint32_t)(((l>>4)&1)*8 + (l&7));
    uint32_t bkh = (uint32_t)((l>>3)&1)*16;
    uint32_t brel[4];
    #pragma unroll
    for (int q = 0; q < 4; q++) brel[q] = (uint32_t)((q*16 + nrb)*XPITCH) + bkh;

    float acc[8][4];
    #pragma unroll
    for (int j = 0; j < 8; j++)
        #pragma unroll
        for (int i = 0; i < 4; i++) acc[j][i] = 0.f;

    float ps[8];        // per-row sumsq partials (row r0+16j)
    #pragma unroll
    for (int j = 0; j < 8; j++) ps[j] = 0.f;

    float4 v[8];

    // ---- prologue: anchors0 cp.async, x0 LDG + convert into buf0 ----
    {
        uint32_t d0 = sb + AOFF + adst;
        cpasync16(d0,      ahsrc);
        cpasync16(d0 + 16, ahsrc + 8);
        CP_COMMIT();
        #pragma unroll
        for (int j = 0; j < 8; j++)
            v[j] = *(const float4*)(xgr + (size_t)(16*j)*Dd);
        #pragma unroll
        for (int j = 0; j < 8; j++) {
            float4 va = v[j];
            ps[j] += va.x*va.x + va.y*va.y + va.z*va.z + va.w*va.w;
            uint32_t p0 = (uint32_t)__bfloat16_as_ushort(__float2bfloat16(va.x))
                        | ((uint32_t)__bfloat16_as_ushort(__float2bfloat16(va.y)) << 16);
            uint32_t p1 = (uint32_t)__bfloat16_as_ushort(__float2bfloat16(va.z))
                        | ((uint32_t)__bfloat16_as_ushort(__float2bfloat16(va.w)) << 16);
            STS64A(sts0 + (uint32_t)(j*16*XPITCH), p0, p1);
        }
        CP_WAIT0();
        __syncthreads();
    }

    // ---- main loop: one sync per chunk ----
    for (int it = 0; it < NCH; it++) {
        int nx = it + 1;
        if (nx < NCH) {
            // LDG next x early (latency hides under MMA)
            const float* xn = xgr + nx*KS;
            #pragma unroll
            for (int j = 0; j < 8; j++)
                v[j] = *(const float4*)(xn + (size_t)(16*j)*Dd);
            // anchors for next chunk -> opposite buffer (safe: last read it-1)
            uint32_t d0 = sb + AOFF + (nx&1)*ABUF + adst;
            cpasync16(d0,      ahsrc + nx*KS);
            cpasync16(d0 + 16, ahsrc + nx*KS + 8);
            CP_COMMIT();
        }

        // MMA on buffers it&1
        uint32_t xA  = aAddrX + (uint32_t)((it&1)*XBUFSZ);
        uint32_t abH = sb + AOFF + (it&1)*ABUF;
        #pragma unroll
        for (int ks = 0; ks < 4; ks++) {
            uint32_t ko = ks*32;
            uint32_t ahf[4];
            ldsm4(ahf, xA + ko);
            #pragma unroll
            for (int hh = 0; hh < 2; hh++) {
                uint32_t bh[8];
                ldsm4(&bh[0], abH + brel[2*hh]   + ko);
                ldsm4(&bh[4], abH + brel[2*hh+1] + ko);
                mma16816(acc[4*hh+0], ahf, &bh[0]);
                mma16816(acc[4*hh+1], ahf, &bh[2]);
                mma16816(acc[4*hh+2], ahf, &bh[4]);
                mma16816(acc[4*hh+3], ahf, &bh[6]);
            }
        }

        // convert + store next x chunk into opposite buffer
        if (nx < NCH) {
            uint32_t sx = sts0 + (uint32_t)((nx&1)*XBUFSZ);
            #pragma unroll
            for (int j = 0; j < 8; j++) {
                float4 va = v[j];
                ps[j] += va.x*va.x + va.y*va.y + va.z*va.z + va.w*va.w;
                uint32_t p0 = (uint32_t)__bfloat16_as_ushort(__float2bfloat16(va.x))
                            | ((uint32_t)__bfloat16_as_ushort(__float2bfloat16(va.y)) << 16);
                uint32_t p1 = (uint32_t)__bfloat16_as_ushort(__float2bfloat16(va.z))
                            | ((uint32_t)__bfloat16_as_ushort(__float2bfloat16(va.w)) << 16);
                STS64A(sx + (uint32_t)(j*16*XPITCH), p0, p1);
            }
            CP_WAIT0();     // anchors(nx) landed
        }
        __syncthreads();
    }

    // row sumsq: reduce across the 16 lanes sharing each row
    {
        #pragma unroll
        for (int o = 1; o < 16; o <<= 1)
            #pragma unroll
            for (int j = 0; j < 8; j++)
                ps[j] += __shfl_xor_sync(0xffffffffu, ps[j], o);
        if (c4 == 0)
            #pragma unroll
            for (int j = 0; j < 8; j++) rowsq[r0 + 16*j] = ps[j];
    }

    __syncthreads();    // all MMA done; overlay D-tile fp32 [128][65] on x buffers
    {
        float* ds = (float*)dsm;
        int row0 = w*16 + (l >> 2);
        int cb = 2*(l & 3);
        #pragma unroll
        for (int j = 0; j < 8; j++) {
            int col = j*8 + cb;
            ds[row0*GS_PAD + col]       = acc[j][0];
            ds[row0*GS_PAD + col + 1]   = acc[j][1];
            ds[(row0+8)*GS_PAD + col]   = acc[j][2];
            ds[(row0+8)*GS_PAD + col+1] = acc[j][3];
        }
    }
    __syncthreads();

    // ---- split-half epilogue: 256 threads, 2 threads per point ----
    int p    = t & 127;
    int half = t >> 7;
    int cb0  = half * 32;
    const float* ds = (const float*)dsm;
    float* ds2 = (float*)(dsm + DS2OFF);   // [64][128]

    float r2   = rowsq[p];
    float rr   = fmaxf(sqrtf(r2), 1e-12f);
    float invr = 1.0f / rr;
    float xnsq = r2 * invr * invr;
    float base = xnsq - 1.0f;
    float n2i  = -2.0f * invr;

    // pass 1: inv-dist cubic; per-half first-max
    float mx = -INFINITY;
    int arg = cb0;
    #pragma unroll 8
    for (int cc = 0; cc < 32; cc++) {
        int c = cb0 + cc;
        float g     = ds[p*GS_PAD + c];
        float2 aux  = sAux[c];
        float delta = fmaf(n2i, g, base);       // sq - (1+A2)
        float u     = delta * aux.y;
        float pp    = fmaf(u, -0.3125f, 0.375f);
        pp          = fmaf(u, pp, -0.5f);
        pp          = fmaf(u, pp, 1.0f);
        float inv   = aux.x * pp;
        if (u*u > 0.04f)                        // |u|>0.2: rare exact fallback
            inv = rsqrtf(fmaxf(delta + 1.0f + sA2[c], 1e-24f));
        ds2[c*TM + p] = inv;
        if (inv > mx) { mx = inv; arg = c; }
    }
    s_h[half][p] = mx; s_ha[half][p] = arg;
    __syncthreads();
    float m0 = s_h[0][p], m1 = s_h[1][p];
    float mxc = (m1 > m0) ? m1 : m0;
    int argc = (m1 > m0) ? s_ha[1][p] : s_ha[0][p];   // tie -> half0 (lower c) = first-max
    __syncthreads();

    // pass 2: cubic exp(inv - mx)
    float Z = 0.f;
    #pragma unroll 8
    for (int cc = 0; cc < 32; cc++) {
        int c = cb0 + cc;
        float u2 = ds2[c*TM + p] - mxc;
        float e  = fmaf(u2, 0.16666667f, 0.5f);
        e        = fmaf(u2, e, 1.0f);
        e        = fmaf(u2, e, 1.0f);
        if (u2 < -0.0625f) e = expf(u2);        // rare exact fallback
        Z += e;
        ds2[c*TM + p] = e;
    }
    s_h[half][p] = Z;
    __syncthreads();
    if (half == 0) {
        s_sc[p] = invr / (s_h[0][p] + s_h[1][p]);
        int n = n0 + p;
        if (n < maskb) atomicAdd(&d_counts[b*Cc + argc], 1);
    }
    __syncthreads();

    // coalesced transposed fp16 score store with per-row scale folded in
    {
        int bpos = blk * TM;
        for (int i = t; i < Cc*TM/2; i += 256) {
            int c  = i >> 6;            // 64 half2 pairs per c row
            int pr = (i & 63) * 2;
            float w0 = ds2[c*TM + pr]     * s_sc[pr];
            float w1 = ds2[c*TM + pr + 1] * s_sc[pr + 1];
            *(__half2*)&d_scoreT[(size_t)c*NP + bpos + pr] = __floats2half2_rn(w0, w1);
        }
    }
}

// ---------------- KB: per-batch mode cluster (warp-parallel, first-max) ----------------
__global__ void kb_index() {
    int b = blockIdx.x, l = threadIdx.x;
    int v0 = d_counts[b*Cc + l];
    int v1 = d_counts[b*Cc + l + 32];
    // pack: count<<6 | (63-c)  -> max picks highest count, lowest c on tie
    int p0 = (v0 << 6) | (63 - l);
    int p1 = (v1 << 6) | (63 - (l + 32));
    int p = max(p0, p1);
    #pragma unroll
    for (int o = 16; o; o >>= 1) p = max(p, __shfl_xor_sync(0xffffffffu, p, o));
    if (l == 0) d_index[b] = 63 - (p & 63);
}

// ---------------- KC: pure streaming weighted sum (round-7 config) ----------------
__global__ __launch_bounds__(256, 3)
void kc_feature(const float* __restrict__ x, const void* __restrict__ mask) {
    __shared__ float sfeat[Dd];
    int t = threadIdx.x, w = t >> 5, l = t & 31;
    int b = blockIdx.x >> 5, s = blockIdx.x & (SLICES - 1);   // b-major (locality)
    int maskb = read_mask(mask, b);
    int idx = d_index[b];
    const __half* scp = d_scoreT + (size_t)idx*NP + (size_t)b*Nn;
    const float* xb  = x + (size_t)b*Nn*Dd;

    float4 acc[4];
    #pragma unroll
    for (int j = 0; j < 4; j++) acc[j] = make_float4(0.f,0.f,0.f,0.f);

    int ws = (s << 3) + w;                      // warp slot 0..255
    for (int n = ws; n < maskb; n += 512) {
        int n2 = n + 256;
        bool has2 = n2 < maskb;
        int n2c = has2 ? n2 : n;
        float w1 = __half2float(__ldg(scp + n));
        float w2 = has2 ? __half2float(__ldg(scp + n2)) : 0.f;
        const float4* xp1 = (const float4*)(xb + (size_t)n*Dd);
        const float4* xp2 = (const float4*)(xb + (size_t)n2c*Dd);
        float4 x1[4], x2[4];
        #pragma unroll
        for (int j = 0; j < 4; j++) { x1[j] = xp1[l + 32*j]; x2[j] = xp2[l + 32*j]; }
        #pragma unroll
        for (int j = 0; j < 4; j++) {
            acc[j].x += x1[j].x*w1 + x2[j].x*w2;
            acc[j].y += x1[j].y*w1 + x2[j].y*w2;
            acc[j].z += x1[j].z*w1 + x2[j].z*w2;
            acc[j].w += x1[j].w*w1 + x2[j].w*w2;
        }
    }

    sfeat[t] = 0.f; sfeat[t + 256] = 0.f;
    __syncthreads();
    #pragma unroll
    for (int j = 0; j < 4; j++) {
        int base = 4*(l + 32*j);
        atomicAdd(&sfeat[base+0], acc[j].x);
        atomicAdd(&sfeat[base+1], acc[j].y);
        atomicAdd(&sfeat[base+2], acc[j].z);
        atomicAdd(&sfeat[base+3], acc[j].w);
    }
    __syncthreads();
    float* pp = &d_partial[(size_t)(b*SLICES + s) * Dd];
    pp[t] = sfeat[t]; pp[t + 256] = sfeat[t + 256];
}

// ---------------- KD: deterministic partial reduction ----------------
__global__ void kd_reduce(float* __restrict__ out) {
    int b = blockIdx.x, t = threadIdx.x;
    for (int d = t; d < Dd; d += 256) {
        float s = 0.f;
        #pragma unroll 8
        for (int j = 0; j < SLICES; j++)
            s += d_partial[(size_t)(b*SLICES + j)*Dd + d];
        out[b*Dd + d] = s;
    }
}

extern "C" void kernel_launch(void* const* d_in, const int* in_sizes, int n_in,
                              void* d_out, int out_size) {
    const float* x       = (const float*)d_in[0];
    const void*  mask    = d_in[1];
    const float* anchors = (const float*)d_in[2];
    float* out = (float*)d_out;

    cudaFuncSetAttribute(ka_mma, cudaFuncAttributeMaxDynamicSharedMemorySize, SMEM_DYN);

    k0_init<<<Cc, 256>>>(anchors);
    ka_mma<<<NP/TM, 256, SMEM_DYN>>>(x, mask);          // 1024 CTAs
    kb_index<<<Bb, 32>>>();
    kc_feature<<<Bb*SLICES, 256>>>(x, mask);            // 1024 CTAs
    kd_reduce<<<Bb, 256>>>(out);
}

// round 12
// speedup vs baseline: 1.2843x; 1.0608x over previous
#include <cuda_runtime.h>
#include <cuda_bf16.h>
#include <cuda_fp16.h>
#include <math.h>
#include <stdint.h>

#define Bb 32
#define Nn 4096
#define Dd 512
#define Cc 64
#define NP (Bb*Nn)      // 131072 points
#define TM 128          // points per CTA tile
#define KS 64           // fp32 K elems per chunk
#define NCH (Dd/KS)     // 8 chunks

#define XPITCH 144      // bytes per smem row (64 bf16 + pad)
#define XBUFSZ 18432    // one x buffer: 128*144
#define AOFF 36864      // anchor double buffer base
#define ABUF 9216       // per-buffer anchors: 64*144
#define DS2OFF 55296    // candidate-weight tile [64][128] fp32
#define SMEM_DYN 88064  // 55296 + 32768
#define GS_PAD 65

#define SLICES 32       // pass-C slices per batch

// ---------------- scratch ----------------
__device__ float  d_anorm2[Cc];
__device__ float2 d_aux[Cc];        // {r0 = 1/sqrt(1+A2), invm = 1/(1+A2)}
__device__ int    d_counts[Bb*Cc];
__device__ int    d_done[Bb];
__device__ float  d_partial[Bb*SLICES*Dd];
__device__ __align__(16) __nv_bfloat16 d_ahi[Cc*Dd];
__device__ __align__(16) __half d_scoreT[(size_t)Cc*NP];  // [C][B*N] fp16 weights

// ---------------- helpers ----------------
__device__ __forceinline__ uint32_t smem_u32(const void* p) {
    uint32_t a;
    asm("{ .reg .u64 t; cvta.to.shared.u64 t, %1; cvt.u32.u64 %0, t; }" : "=r"(a) : "l"(p));
    return a;
}
#define STS64A(addr, a,b) \
    asm volatile("st.shared.v2.b32 [%0], {%1,%2};" :: "r"(addr),"r"(a),"r"(b) : "memory")

__device__ __forceinline__ void cpasync16(uint32_t dst, const void* src) {
    asm volatile("cp.async.ca.shared.global [%0], [%1], 16;" :: "r"(dst), "l"(src) : "memory");
}
#define CP_COMMIT() asm volatile("cp.async.commit_group;" ::: "memory")
#define CP_WAIT0()  asm volatile("cp.async.wait_group 0;" ::: "memory")

__device__ __forceinline__ void ldsm4(uint32_t* r, uint32_t a) {
    asm volatile("ldmatrix.sync.aligned.m8n8.x4.shared.b16 {%0,%1,%2,%3}, [%4];"
        : "=r"(r[0]),"=r"(r[1]),"=r"(r[2]),"=r"(r[3]) : "r"(a));
}
__device__ __forceinline__ void mma16816(float* c, const uint32_t* a, const uint32_t* b) {
    asm volatile("mma.sync.aligned.m16n8k16.row.col.f32.bf16.bf16.f32 "
        "{%0,%1,%2,%3}, {%4,%5,%6,%7}, {%8,%9}, {%0,%1,%2,%3};"
        : "+f"(c[0]),"+f"(c[1]),"+f"(c[2]),"+f"(c[3])
        : "r"(a[0]),"r"(a[1]),"r"(a[2]),"r"(a[3]), "r"(b[0]),"r"(b[1]));
}

// mask may arrive as int32 or int64; values in [1,4096] so high word of elem0 is 0 iff int64
__device__ __forceinline__ int read_mask(const void* m, int b) {
    const int* mi = (const int*)m;
    if (mi[1] == 0) return (int)(((const long long*)m)[b]);
    return mi[b];
}

// ---------------- K0: anchor norms/aux + bf16 convert + zero counts/done ----------------
__global__ void k0_init(const float* __restrict__ anchors) {
    __shared__ float wsum[8];
    int c = blockIdx.x, t = threadIdx.x, w = t >> 5, l = t & 31;
    if (c == 0) {
        for (int i = t; i < Bb*Cc; i += 256) d_counts[i] = 0;
        if (t < Bb) d_done[t] = 0;
    }
    float2 v = ((const float2*)(anchors + (size_t)c*Dd))[t];
    uint32_t lo = (uint32_t)__bfloat16_as_ushort(__float2bfloat16(v.x));
    uint32_t hi = (uint32_t)__bfloat16_as_ushort(__float2bfloat16(v.y));
    *(uint32_t*)&d_ahi[(size_t)c*Dd + 2*t] = lo | (hi << 16);
    float s = v.x*v.x + v.y*v.y;
    #pragma unroll
    for (int o = 16; o; o >>= 1) s += __shfl_xor_sync(0xffffffffu, s, o);
    if (l == 0) wsum[w] = s;
    __syncthreads();
    if (t == 0) {
        float tot = 0.f;
        #pragma unroll
        for (int j = 0; j < 8; j++) tot += wsum[j];
        d_anorm2[c] = tot;
        double m = 1.0 + (double)tot;
        d_aux[c] = make_float2((float)(1.0/sqrt(m)), (float)(1.0/m));
    }
}

// ---------------- KA: mma.sync bf16 GEMM (double-buffered, occ 2) + poly softmax ----------------
__global__ __launch_bounds__(256, 2)
void ka_mma(const float* __restrict__ x, const void* __restrict__ mask) {
    extern __shared__ __align__(16) char dsm[];
    __shared__ float rowsq[TM];
    __shared__ float s_sc[TM];
    __shared__ float sA2[Cc];
    __shared__ float2 sAux[Cc];
    __shared__ float s_h[2][TM];
    __shared__ int   s_ha[2][TM];

    int t = threadIdx.x, w = t >> 5, l = t & 31;
    int blk = blockIdx.x;
    int b = blk >> 5, n0 = (blk & 31) * TM;
    int maskb = read_mask(mask, b);
    if (n0 >= maskb) return;            // fully invalid tile

    if (t < Cc) { sA2[t] = d_anorm2[t]; sAux[t] = d_aux[t]; }
    uint32_t sb = smem_u32(dsm);

    // coalesced x staging: thread t -> rows r0+16j (j=0..7), float4 col c4
    int r0 = t >> 4, c4 = t & 15;
    const float* xgr = x + ((size_t)(b*Nn + n0) + r0) * Dd + c4*4;
    uint32_t sts0 = sb + (uint32_t)(r0*XPITCH + c4*8);
    // anchor cp.async mapping: row ra (0..63), quarter aq (16 bf16 = 32B)
    int ra = t >> 2, aq = t & 3;
    uint32_t adst = (uint32_t)(ra*XPITCH + aq*32);
    const __nv_bfloat16* ahsrc = d_ahi + (size_t)ra*Dd + aq*16;

    // ldmatrix lane addresses
    uint32_t mrow = (uint32_t)(w*16 + ((l>>3)&1)*8 + (l&7));
    uint32_t aAddrX = sb + mrow*XPITCH + ((l>>4)&1)*16;
    uint32_t nrb = (uint32_t)(((l>>4)&1)*8 + (l&7));
    uint32_t bkh = (uint32_t)((l>>3)&1)*16;
    uint32_t brel[4];
    #pragma unroll
    for (int q = 0; q < 4; q++) brel[q] = (uint32_t)((q*16 + nrb)*XPITCH) + bkh;

    float acc[8][4];
    #pragma unroll
    for (int j = 0; j < 8; j++)
        #pragma unroll
        for (int i = 0; i < 4; i++) acc[j][i] = 0.f;

    float ps[8];        // per-row sumsq partials (row r0+16j)
    #pragma unroll
    for (int j = 0; j < 8; j++) ps[j] = 0.f;

    float4 v[8];

    // ---- prologue: anchors0 cp.async, x0 LDG + convert into buf0 ----
    {
        uint32_t d0 = sb + AOFF + adst;
        cpasync16(d0,      ahsrc);
        cpasync16(d0 + 16, ahsrc + 8);
        CP_COMMIT();
        #pragma unroll
        for (int j = 0; j < 8; j++)
            v[j] = *(const float4*)(xgr + (size_t)(16*j)*Dd);
        #pragma unroll
        for (int j = 0; j < 8; j++) {
            float4 va = v[j];
            ps[j] += va.x*va.x + va.y*va.y + va.z*va.z + va.w*va.w;
            uint32_t p0 = (uint32_t)__bfloat16_as_ushort(__float2bfloat16(va.x))
                        | ((uint32_t)__bfloat16_as_ushort(__float2bfloat16(va.y)) << 16);
            uint32_t p1 = (uint32_t)__bfloat16_as_ushort(__float2bfloat16(va.z))
                        | ((uint32_t)__bfloat16_as_ushort(__float2bfloat16(va.w)) << 16);
            STS64A(sts0 + (uint32_t)(j*16*XPITCH), p0, p1);
        }
        CP_WAIT0();
        __syncthreads();
    }

    // ---- main loop: one sync per chunk ----
    for (int it = 0; it < NCH; it++) {
        int nx = it + 1;
        if (nx < NCH) {
            // LDG next x early (latency hides under MMA)
            const float* xn = xgr + nx*KS;
            #pragma unroll
            for (int j = 0; j < 8; j++)
                v[j] = *(const float4*)(xn + (size_t)(16*j)*Dd);
            // anchors for next chunk -> opposite buffer (safe: last read it-1)
            uint32_t d0 = sb + AOFF + (nx&1)*ABUF + adst;
            cpasync16(d0,      ahsrc + nx*KS);
            cpasync16(d0 + 16, ahsrc + nx*KS + 8);
            CP_COMMIT();
        }

        // MMA on buffers it&1
        uint32_t xA  = aAddrX + (uint32_t)((it&1)*XBUFSZ);
        uint32_t abH = sb + AOFF + (it&1)*ABUF;
        #pragma unroll
        for (int ks = 0; ks < 4; ks++) {
            uint32_t ko = ks*32;
            uint32_t ahf[4];
            ldsm4(ahf, xA + ko);
            #pragma unroll
            for (int hh = 0; hh < 2; hh++) {
                uint32_t bh[8];
                ldsm4(&bh[0], abH + brel[2*hh]   + ko);
                ldsm4(&bh[4], abH + brel[2*hh+1] + ko);
                mma16816(acc[4*hh+0], ahf, &bh[0]);
                mma16816(acc[4*hh+1], ahf, &bh[2]);
                mma16816(acc[4*hh+2], ahf, &bh[4]);
                mma16816(acc[4*hh+3], ahf, &bh[6]);
            }
        }

        // convert + store next x chunk into opposite buffer
        if (nx < NCH) {
            uint32_t sx = sts0 + (uint32_t)((nx&1)*XBUFSZ);
            #pragma unroll
            for (int j = 0; j < 8; j++) {
                float4 va = v[j];
                ps[j] += va.x*va.x + va.y*va.y + va.z*va.z + va.w*va.w;
                uint32_t p0 = (uint32_t)__bfloat16_as_ushort(__float2bfloat16(va.x))
                            | ((uint32_t)__bfloat16_as_ushort(__float2bfloat16(va.y)) << 16);
                uint32_t p1 = (uint32_t)__bfloat16_as_ushort(__float2bfloat16(va.z))
                            | ((uint32_t)__bfloat16_as_ushort(__float2bfloat16(va.w)) << 16);
                STS64A(sx + (uint32_t)(j*16*XPITCH), p0, p1);
            }
            CP_WAIT0();     // anchors(nx) landed
        }
        __syncthreads();
    }

    // row sumsq: reduce across the 16 lanes sharing each row
    {
        #pragma unroll
        for (int o = 1; o < 16; o <<= 1)
            #pragma unroll
            for (int j = 0; j < 8; j++)
                ps[j] += __shfl_xor_sync(0xffffffffu, ps[j], o);
        if (c4 == 0)
            #pragma unroll
            for (int j = 0; j < 8; j++) rowsq[r0 + 16*j] = ps[j];
    }

    __syncthreads();    // all MMA done; overlay D-tile fp32 [128][65] on x buffers
    {
        float* ds = (float*)dsm;
        int row0 = w*16 + (l >> 2);
        int cb = 2*(l & 3);
        #pragma unroll
        for (int j = 0; j < 8; j++) {
            int col = j*8 + cb;
            ds[row0*GS_PAD + col]       = acc[j][0];
            ds[row0*GS_PAD + col + 1]   = acc[j][1];
            ds[(row0+8)*GS_PAD + col]   = acc[j][2];
            ds[(row0+8)*GS_PAD + col+1] = acc[j][3];
        }
    }
    __syncthreads();

    // ---- split-half epilogue: 256 threads, 2 threads per point ----
    int p    = t & 127;
    int half = t >> 7;
    int cb0  = half * 32;
    const float* ds = (const float*)dsm;
    float* ds2 = (float*)(dsm + DS2OFF);   // [64][128]

    float r2   = rowsq[p];
    float rr   = fmaxf(sqrtf(r2), 1e-12f);
    float invr = 1.0f / rr;
    float xnsq = r2 * invr * invr;
    float base = xnsq - 1.0f;
    float n2i  = -2.0f * invr;

    // pass 1: inv-dist cubic; per-half first-max
    float mx = -INFINITY;
    int arg = cb0;
    #pragma unroll 8
    for (int cc = 0; cc < 32; cc++) {
        int c = cb0 + cc;
        float g     = ds[p*GS_PAD + c];
        float2 aux  = sAux[c];
        float delta = fmaf(n2i, g, base);       // sq - (1+A2)
        float u     = delta * aux.y;
        float pp    = fmaf(u, -0.3125f, 0.375f);
        pp          = fmaf(u, pp, -0.5f);
        pp          = fmaf(u, pp, 1.0f);
        float inv   = aux.x * pp;
        if (u*u > 0.04f)                        // |u|>0.2: rare exact fallback
            inv = rsqrtf(fmaxf(delta + 1.0f + sA2[c], 1e-24f));
        ds2[c*TM + p] = inv;
        if (inv > mx) { mx = inv; arg = c; }
    }
    s_h[half][p] = mx; s_ha[half][p] = arg;
    __syncthreads();
    float m0 = s_h[0][p], m1 = s_h[1][p];
    float mxc = (m1 > m0) ? m1 : m0;
    int argc = (m1 > m0) ? s_ha[1][p] : s_ha[0][p];   // tie -> half0 (lower c) = first-max
    __syncthreads();

    // pass 2: cubic exp(inv - mx)
    float Z = 0.f;
    #pragma unroll 8
    for (int cc = 0; cc < 32; cc++) {
        int c = cb0 + cc;
        float u2 = ds2[c*TM + p] - mxc;
        float e  = fmaf(u2, 0.16666667f, 0.5f);
        e        = fmaf(u2, e, 1.0f);
        e        = fmaf(u2, e, 1.0f);
        if (u2 < -0.0625f) e = expf(u2);        // rare exact fallback
        Z += e;
        ds2[c*TM + p] = e;
    }
    s_h[half][p] = Z;
    __syncthreads();
    if (half == 0) {
        s_sc[p] = invr / (s_h[0][p] + s_h[1][p]);
        int n = n0 + p;
        if (n < maskb) atomicAdd(&d_counts[b*Cc + argc], 1);
    }
    __syncthreads();

    // coalesced transposed fp16 score store with per-row scale folded in
    {
        int bpos = blk * TM;
        for (int i = t; i < Cc*TM/2; i += 256) {
            int c  = i >> 6;            // 64 half2 pairs per c row
            int pr = (i & 63) * 2;
            float w0 = ds2[c*TM + pr]     * s_sc[pr];
            float w1 = ds2[c*TM + pr + 1] * s_sc[pr + 1];
            *(__half2*)&d_scoreT[(size_t)c*NP + bpos + pr] = __floats2half2_rn(w0, w1);
        }
    }
}

// ---------------- KC: mode-index + streaming weighted sum + last-block reduce ----------------
__global__ __launch_bounds__(256, 3)
void kc_feature(const float* __restrict__ x, const void* __restrict__ mask,
                float* __restrict__ out) {
    __shared__ float sfeat[Dd];
    __shared__ int s_idx;
    __shared__ int s_last;
    int t = threadIdx.x, w = t >> 5, l = t & 31;
    int b = blockIdx.x >> 5, s = blockIdx.x & (SLICES - 1);   // b-major (locality)
    int maskb = read_mask(mask, b);

    // fold of kb_index: warp 0 computes mode cluster (first-max tie-break)
    if (w == 0) {
        int v0 = d_counts[b*Cc + l];
        int v1 = d_counts[b*Cc + l + 32];
        int p0 = (v0 << 6) | (63 - l);
        int p1 = (v1 << 6) | (63 - (l + 32));
        int p = max(p0, p1);
        #pragma unroll
        for (int o = 16; o; o >>= 1) p = max(p, __shfl_xor_sync(0xffffffffu, p, o));
        if (l == 0) s_idx = 63 - (p & 63);
    }
    __syncthreads();
    int idx = s_idx;

    const __half* scp = d_scoreT + (size_t)idx*NP + (size_t)b*Nn;
    const float* xb  = x + (size_t)b*Nn*Dd;

    float4 acc[4];
    #pragma unroll
    for (int j = 0; j < 4; j++) acc[j] = make_float4(0.f,0.f,0.f,0.f);

    int ws = (s << 3) + w;                      // warp slot 0..255
    for (int n = ws; n < maskb; n += 512) {
        int n2 = n + 256;
        bool has2 = n2 < maskb;
        int n2c = has2 ? n2 : n;
        float w1 = __half2float(__ldg(scp + n));
        float w2 = has2 ? __half2float(__ldg(scp + n2)) : 0.f;
        const float4* xp1 = (const float4*)(xb + (size_t)n*Dd);
        const float4* xp2 = (const float4*)(xb + (size_t)n2c*Dd);
        float4 x1[4], x2[4];
        #pragma unroll
        for (int j = 0; j < 4; j++) { x1[j] = xp1[l + 32*j]; x2[j] = xp2[l + 32*j]; }
        #pragma unroll
        for (int j = 0; j < 4; j++) {
            acc[j].x += x1[j].x*w1 + x2[j].x*w2;
            acc[j].y += x1[j].y*w1 + x2[j].y*w2;
            acc[j].z += x1[j].z*w1 + x2[j].z*w2;
            acc[j].w += x1[j].w*w1 + x2[j].w*w2;
        }
    }

    sfeat[t] = 0.f; sfeat[t + 256] = 0.f;
    __syncthreads();
    #pragma unroll
    for (int j = 0; j < 4; j++) {
        int base = 4*(l + 32*j);
        atomicAdd(&sfeat[base+0], acc[j].x);
        atomicAdd(&sfeat[base+1], acc[j].y);
        atomicAdd(&sfeat[base+2], acc[j].z);
        atomicAdd(&sfeat[base+3], acc[j].w);
    }
    __syncthreads();
    float* pp = &d_partial[(size_t)(b*SLICES + s) * Dd];
    pp[t] = sfeat[t]; pp[t + 256] = sfeat[t + 256];

    // fold of kd_reduce: last block of batch b reduces all 32 partials
    __threadfence();
    if (t == 0) {
        int old = atomicAdd(&d_done[b], 1);
        s_last = (old == SLICES - 1) ? 1 : 0;
    }
    __syncthreads();
    if (s_last) {
        for (int d = t; d < Dd; d += 256) {
            float sum = 0.f;
            #pragma unroll 8
            for (int j = 0; j < SLICES; j++)
                sum += d_partial[(size_t)(b*SLICES + j)*Dd + d];
            out[b*Dd + d] = sum;
        }
    }
}

extern "C" void kernel_launch(void* const* d_in, const int* in_sizes, int n_in,
                              void* d_out, int out_size) {
    const float* x       = (const float*)d_in[0];
    const void*  mask    = d_in[1];
    const float* anchors = (const float*)d_in[2];
    float* out = (float*)d_out;

    cudaFuncSetAttribute(ka_mma, cudaFuncAttributeMaxDynamicSharedMemorySize, SMEM_DYN);

    k0_init<<<Cc, 256>>>(anchors);
    ka_mma<<<NP/TM, 256, SMEM_DYN>>>(x, mask);          // 1024 CTAs
    kc_feature<<<Bb*SLICES, 256>>>(x, mask, out);       // 1024 CTAs
}